// round 11
// baseline (speedup 1.0000x reference)
#include <cuda_runtime.h>
#include <cuda_fp16.h>
#include <cstdint>
#include <math.h>

// Problem constants
#define N0c 100000
#define N1c 40000
#define N2c 10000
#define E1c 640000
#define E2c 160000
#define Dc  256
#define DOUTc 128

#define PREP_BLOCKS 148

// ---------------- scratch (device globals) -----------------------------------
__device__ __half g_xh[(size_t)N0c * Dc];   // fp16 copy of x
__device__ __half g_h[(size_t)N1c * Dc];    // fp16 hidden layer
__device__ int   g_cnt[N1c + N2c + 3];      // counts + 3 barrier slots
__device__ int   g_offs1[N1c + 1];
__device__ int   g_offs2[N2c + 1];
__device__ int   g_cur1[N1c];
__device__ int   g_cur2[N2c];
__device__ int   g_eid1[E1c];
__device__ int   g_eid2[E2c];

__device__ __half g_A1[(size_t)N1c * 512];
__device__ __half g_A2[(size_t)N2c * 512];
__device__ __half g_W1[(size_t)Dc * 512];
__device__ __half g_W2[(size_t)DOUTc * 512];

// ---------------- PTX helpers ---------------------------------------------------

__device__ __forceinline__ uint32_t smem_u32(const void* p) {
    uint32_t a;
    asm("{ .reg .u64 t; cvta.to.shared.u64 t, %1; cvt.u32.u64 %0, t; }" : "=r"(a) : "l"(p));
    return a;
}

__device__ __forceinline__ void cp16(uint32_t dst, const void* src, uint32_t sz) {
    asm volatile("cp.async.ca.shared.global [%0], [%1], 16, %2;"
                 :: "r"(dst), "l"(src), "r"(sz) : "memory");
}
__device__ __forceinline__ void cp_commit() {
    asm volatile("cp.async.commit_group;" ::: "memory");
}
template <int N>
__device__ __forceinline__ void cp_wait() {
    asm volatile("cp.async.wait_group %0;" :: "n"(N) : "memory");
}

__device__ __forceinline__ void mma16816h(float* c, const uint32_t* a, const uint32_t* b) {
    asm volatile(
        "mma.sync.aligned.m16n8k16.row.col.f32.f16.f16.f32 "
        "{%0,%1,%2,%3}, {%4,%5,%6,%7}, {%8,%9}, {%0,%1,%2,%3};"
        : "+f"(c[0]), "+f"(c[1]), "+f"(c[2]), "+f"(c[3])
        : "r"(a[0]), "r"(a[1]), "r"(a[2]), "r"(a[3]), "r"(b[0]), "r"(b[1]));
}

__device__ __forceinline__ void ldsm4(uint32_t* r, uint32_t addr) {
    asm volatile("ldmatrix.sync.aligned.m8n8.x4.shared.b16 {%0,%1,%2,%3}, [%4];"
                 : "=r"(r[0]), "=r"(r[1]), "=r"(r[2]), "=r"(r[3]) : "r"(addr));
}

__device__ __forceinline__ uint32_t pack_h2(float a, float b) {
    __half2 h = __floats2half2_rn(a, b);
    return *(uint32_t*)&h;
}

// ---------------- fp16 gather-mean helper -------------------------------------------

__device__ __forceinline__ void acc8(float* s, uint4 v) {
    __half2* p = (__half2*)&v;
    #pragma unroll
    for (int q = 0; q < 4; q++) {
        float2 f = __half22float2(p[q]);
        s[2 * q]     += f.x;
        s[2 * q + 1] += f.y;
    }
}

__device__ __forceinline__ void gather_row_h(const __half* __restrict__ X,
                                             const int* __restrict__ offs,
                                             const int* __restrict__ eid,
                                             __half* __restrict__ A,
                                             int w, int lane) {
    int beg = offs[w], end = offs[w + 1];
    float s[8];
    #pragma unroll
    for (int q = 0; q < 8; q++) s[q] = 0.0f;

    int e = beg;
    for (; e + 1 < end; e += 2) {
        int i0 = eid[e], i1 = eid[e + 1];
        uint4 v0 = __ldg((const uint4*)(X + (size_t)i0 * Dc) + lane);
        uint4 v1 = __ldg((const uint4*)(X + (size_t)i1 * Dc) + lane);
        acc8(s, v0);
        acc8(s, v1);
    }
    if (e < end) {
        uint4 v0 = __ldg((const uint4*)(X + (size_t)eid[e] * Dc) + lane);
        acc8(s, v0);
    }
    float invd = 1.0f / (float)max(end - beg, 1);

    uint4 m;
    m.x = pack_h2(s[0] * invd, s[1] * invd);
    m.y = pack_h2(s[2] * invd, s[3] * invd);
    m.z = pack_h2(s[4] * invd, s[5] * invd);
    m.w = pack_h2(s[6] * invd, s[7] * invd);

    uint4 self = __ldg((const uint4*)(X + (size_t)w * Dc) + lane);

    __stcs((uint4*)(A + (size_t)w * 512) + lane, m);
    __stcs((uint4*)(A + (size_t)w * 512 + 256) + lane, self);
}

// ---------------- prep megakernel ----------------------------------------------------
// Phases: count -> (scan blocks 0,1 | convert blocks >=2) -> fill -> [grid barrier]
//         -> gather1.  SW barriers via counters in cnt[] (memset-reset each replay).

__global__ void __launch_bounds__(1024, 1)
prep_kernel(const int* __restrict__ src1, const int* __restrict__ dst1,
            const int* __restrict__ src2, const int* __restrict__ dst2,
            int* __restrict__ cnt,
            int* __restrict__ offs1, int* __restrict__ cur1,
            int* __restrict__ offs2, int* __restrict__ cur2,
            int* __restrict__ eid1, int* __restrict__ eid2,
            const float* __restrict__ x, __half* __restrict__ xh,
            const float* __restrict__ W1l, const float* __restrict__ W1r,
            __half* __restrict__ W1_,
            const float* __restrict__ W2l, const float* __restrict__ W2r,
            __half* __restrict__ W2_,
            __half* __restrict__ A1) {
    int* done0 = cnt + N1c + N2c;       // count done
    int* done1 = done0 + 1;             // scans done (==2)
    int* done2 = done0 + 2;             // fill done (==grid)

    // ---- phase A: count ----
    const int total = E1c + E2c;
    for (int i = blockIdx.x * blockDim.x + threadIdx.x; i < total;
         i += gridDim.x * blockDim.x) {
        if (i < E1c) atomicAdd(&cnt[dst1[i]], 1);
        else         atomicAdd(&cnt[N1c + dst2[i - E1c]], 1);
    }
    __syncthreads();
    __threadfence();
    if (threadIdx.x == 0) atomicAdd(done0, 1);

    // ---- phase B: scan (blocks 0,1) | convert (blocks >=2) ----
    if (blockIdx.x < 2) {
        if (threadIdx.x == 0) {
            while (*(volatile int*)done0 < (int)gridDim.x) { }
        }
        __syncthreads();
        __threadfence();

        const int  n  = (blockIdx.x == 0) ? N1c : N2c;
        const int* c  = (blockIdx.x == 0) ? cnt : (cnt + N1c);
        int* offs = (blockIdx.x == 0) ? offs1 : offs2;
        int* cur  = (blockIdx.x == 0) ? cur1 : cur2;

        __shared__ int warpsums[32];
        __shared__ int s_carry;
        const int lane = threadIdx.x & 31;
        const int wid  = threadIdx.x >> 5;
        const int nw   = blockDim.x >> 5;
        if (threadIdx.x == 0) s_carry = 0;
        __syncthreads();
        for (int base = 0; base < n; base += blockDim.x) {
            int i = base + threadIdx.x;
            int v = (i < n) ? c[i] : 0;
            int carry = s_carry;
            int xv = v;
            #pragma unroll
            for (int o = 1; o < 32; o <<= 1) {
                int y = __shfl_up_sync(0xFFFFFFFFu, xv, o);
                if (lane >= o) xv += y;
            }
            if (lane == 31) warpsums[wid] = xv;
            __syncthreads();
            if (wid == 0) {
                int w = (lane < nw) ? warpsums[lane] : 0;
                #pragma unroll
                for (int o = 1; o < 32; o <<= 1) {
                    int y = __shfl_up_sync(0xFFFFFFFFu, w, o);
                    if (lane >= o) w += y;
                }
                warpsums[lane] = w;
            }
            __syncthreads();
            int incl = xv + (wid > 0 ? warpsums[wid - 1] : 0) + carry;
            if (i < n) { offs[i] = incl - v; cur[i] = incl - v; }
            __syncthreads();
            if (threadIdx.x == blockDim.x - 1) s_carry = incl;
            __syncthreads();
        }
        if (threadIdx.x == 0) offs[n] = s_carry;
        __syncthreads();
        __threadfence();
        if (threadIdx.x == 0) atomicAdd(done1, 1);
    } else {
        // convert x -> fp16
        const int nt  = (gridDim.x - 2) * blockDim.x;
        const int tg  = (blockIdx.x - 2) * blockDim.x + threadIdx.x;
        const float4* xf = (const float4*)x;
        const int xiters = N0c * Dc / 8;
        for (int i = tg; i < xiters; i += nt) {
            float4 v0 = xf[2 * i];
            float4 v1 = xf[2 * i + 1];
            uint4 u;
            u.x = pack_h2(v0.x, v0.y);
            u.y = pack_h2(v0.z, v0.w);
            u.z = pack_h2(v1.x, v1.y);
            u.w = pack_h2(v1.z, v1.w);
            ((uint4*)xh)[i] = u;
        }
        for (int i = tg; i < Dc * 512; i += nt) {
            int n = i >> 9, k = i & 511;
            float v = (k < 256) ? W1l[(size_t)k * Dc + n] : W1r[(size_t)(k - 256) * Dc + n];
            W1_[(size_t)n * 512 + k] = __float2half_rn(v);
        }
        for (int i = tg; i < DOUTc * 512; i += nt) {
            int n = i >> 9, k = i & 511;
            float v = (k < 256) ? W2l[(size_t)k * DOUTc + n] : W2r[(size_t)(k - 256) * DOUTc + n];
            W2_[(size_t)n * 512 + k] = __float2half_rn(v);
        }
        __threadfence();   // xh/W visible before fill-done barrier below
    }

    // ---- wait: both scans done ----
    if (threadIdx.x == 0) {
        while (*(volatile int*)done1 < 2) { }
    }
    __syncthreads();

    // ---- phase C: fill (grid-stride, all blocks) ----
    for (int i = blockIdx.x * blockDim.x + threadIdx.x; i < total;
         i += gridDim.x * blockDim.x) {
        if (i < E1c) {
            int pos = atomicAdd(&cur1[dst1[i]], 1);
            eid1[pos] = src1[i];
        } else {
            int j = i - E1c;
            int pos = atomicAdd(&cur2[dst2[j]], 1);
            eid2[pos] = src2[j];
        }
    }
    __syncthreads();
    __threadfence();
    if (threadIdx.x == 0) {
        atomicAdd(done2, 1);
        while (*(volatile int*)done2 < (int)gridDim.x) { }
    }
    __syncthreads();

    // ---- phase D: gather1 (warp per row, grid-stride) ----
    const int lane = threadIdx.x & 31;
    int gw = blockIdx.x * 32 + (threadIdx.x >> 5);
    for (int w = gw; w < N1c; w += gridDim.x * 32)
        gather_row_h(xh, offs1, eid1, A1, w, lane);
}

// ---------------- gather2 -------------------------------------------------------------

__global__ void gather2_kernel(const __half* __restrict__ h,
                               const int* __restrict__ offs2, const int* __restrict__ eid2,
                               __half* __restrict__ A2) {
    int w    = (blockIdx.x * blockDim.x + threadIdx.x) >> 5;
    int lane = threadIdx.x & 31;
    if (w < N2c) gather_row_h(h, offs2, eid2, A2, w, lane);
}

// ---------------- persistent mma.sync fp16 GEMM, BK=64 --------------------------------
// C = act( A@B^T + bias ). Tiles 128x128; NSPLIT N-halves per M tile; persistent grid
// with cross-tile cp.async prefetch (8 even chunks/tile -> stage parity continues).

#define ROWB 144                        // 128B data + 16B pad (conflict-free ldmatrix)
#define MAT_BYTES (128 * ROWB)          // 18432
#define STAGE_BYTES (2 * MAT_BYTES)     // A + B = 36864
#define GEMM_SMEM (2 * STAGE_BYTES)     // 73728; 2 CTAs/SM = 147456 <= 227KB

template <int NTOT, int NSPLIT, int ACT, typename OUT>
__global__ void __launch_bounds__(256, 2)
gemm_mma(const __half* __restrict__ A, const __half* __restrict__ B,
         const float* __restrict__ bias, OUT* __restrict__ C, int M, int nTiles)
{
    extern __shared__ char smem[];
    const uint32_t sbase = smem_u32(smem);
    const int tid  = threadIdx.x;
    const int wid  = tid >> 5;
    const int lane = tid & 31;
    const int wm   = wid >> 2;
    const int wn   = wid & 3;
    const int g    = lane >> 2;
    const int t    = lane & 3;

    const int rowoff = (lane & 7) + ((lane >> 3) & 1) * 8;
    const int koff   = (lane >> 4) * 8;
    const uint32_t lmc = (uint32_t)(rowoff * ROWB + koff * 2);

    if ((int)blockIdx.x >= nTiles) return;

    // stage loader: 2048 x 16B cp.async (8 per thread); mat 0=A, 1=B
    auto load_stage = [&](int s, int k0, int row0, int col0) {
        uint32_t base = sbase + s * STAGE_BYTES;
        #pragma unroll
        for (int q8 = 0; q8 < 8; q8++) {
            int idx  = q8 * 256 + tid;
            int mat  = idx >> 10;
            int slot = idx & 1023;
            int row  = slot >> 3;
            int quar = slot & 7;
            uint32_t dst = base + mat * MAT_BYTES + row * ROWB + quar * 16;
            if (mat == 0) {
                int grow = row0 + row;
                int srow = grow < M ? grow : (M - 1);
                const __half* src = A + (size_t)srow * 512 + k0 + quar * 8;
                cp16(dst, src, grow < M ? 16u : 0u);
            } else {
                const __half* src = B + (size_t)(col0 + row) * 512 + k0 + quar * 8;
                cp16(dst, src, 16u);
            }
        }
    };

    auto tile_row0 = [&](int tl) { return (NSPLIT == 2 ? (tl >> 1) : tl) * 128; };
    auto tile_col0 = [&](int tl) { return (NSPLIT == 2 ? (tl & 1) : 0) * 128; };

    int tile = blockIdx.x;
    load_stage(0, 0, tile_row0(tile), tile_col0(tile));
    cp_commit();

    #pragma unroll 1
    for (; tile < nTiles; tile += gridDim.x) {
        const int row0 = tile_row0(tile);
        const int col0 = tile_col0(tile);
        const int ntile = tile + gridDim.x;

        float acc[4][4][4];
        #pragma unroll
        for (int i = 0; i < 4; i++)
            #pragma unroll
            for (int j = 0; j < 4; j++)
                #pragma unroll
                for (int q = 0; q < 4; q++) acc[i][j][q] = 0.0f;

        #pragma unroll 1
        for (int c = 0; c < 8; c++) {
            // prefetch next chunk (same tile) or next tile's chunk 0
            if (c < 7) {
                load_stage((c + 1) & 1, (c + 1) * 64, row0, col0);
            } else if (ntile < nTiles) {
                load_stage(0, 0, tile_row0(ntile), tile_col0(ntile));
            }
            cp_commit();
            cp_wait<1>();
            __syncthreads();

            const uint32_t st = sbase + (c & 1) * STAGE_BYTES;
            const uint32_t uA = st;
            const uint32_t uB = st + MAT_BYTES;

            #pragma unroll
            for (int kk = 0; kk < 64; kk += 16) {
                const uint32_t kb = (uint32_t)(kk * 2) + lmc;
                uint32_t b2[2][4];
                #pragma unroll
                for (int pp = 0; pp < 2; pp++) {
                    uint32_t nb = (uint32_t)((wn * 32 + pp * 16) * ROWB) + kb;
                    ldsm4(b2[pp], uB + nb);
                }
                #pragma unroll
                for (int i = 0; i < 4; i++) {
                    uint32_t rb = (uint32_t)((wm * 64 + i * 16) * ROWB) + kb;
                    uint32_t ah[4];
                    ldsm4(ah, uA + rb);
                    #pragma unroll
                    for (int j = 0; j < 4; j++) {
                        const int pp = j >> 1, s = j & 1;
                        uint32_t bb[2] = { b2[pp][s], b2[pp][s + 2] };
                        mma16816h(acc[i][j], ah, bb);
                    }
                }
            }
            __syncthreads();
        }

        // epilogue (overlaps next tile's chunk-0 cp.async)
        #pragma unroll
        for (int j = 0; j < 4; j++) {
            int cidx = col0 + wn * 32 + j * 8 + 2 * t;
            float bx = bias[cidx], by = bias[cidx + 1];
            #pragma unroll
            for (int i = 0; i < 4; i++) {
                int r = row0 + wm * 64 + i * 16 + g;
                float v0 = acc[i][j][0] + bx;
                float v1 = acc[i][j][1] + by;
                float v2 = acc[i][j][2] + bx;
                float v3 = acc[i][j][3] + by;
                if (ACT == 0) {
                    v0 = fmaxf(v0, 0.f); v1 = fmaxf(v1, 0.f);
                    v2 = fmaxf(v2, 0.f); v3 = fmaxf(v3, 0.f);
                } else {
                    v0 = 1.0f / (1.0f + expf(-v0));
                    v1 = 1.0f / (1.0f + expf(-v1));
                    v2 = 1.0f / (1.0f + expf(-v2));
                    v3 = 1.0f / (1.0f + expf(-v3));
                }
                if (sizeof(OUT) == 2) {
                    if (r < M)
                        *(uint32_t*)((__half*)C + (size_t)r * NTOT + cidx) = pack_h2(v0, v1);
                    if (r + 8 < M)
                        *(uint32_t*)((__half*)C + (size_t)(r + 8) * NTOT + cidx) = pack_h2(v2, v3);
                } else {
                    if (r < M)
                        *(float2*)((float*)C + (size_t)r * NTOT + cidx) = make_float2(v0, v1);
                    if (r + 8 < M)
                        *(float2*)((float*)C + (size_t)(r + 8) * NTOT + cidx) = make_float2(v2, v3);
                }
            }
        }
    }
}

// ---------------- launch ----------------------------------------------------------

extern "C" void kernel_launch(void* const* d_in, const int* in_sizes, int n_in,
                              void* d_out, int out_size) {
    const float* x    = (const float*)d_in[0];
    const float* W1l  = (const float*)d_in[1];
    const float* b1   = (const float*)d_in[2];
    const float* W1r  = (const float*)d_in[3];
    const float* W2l  = (const float*)d_in[4];
    const float* b2   = (const float*)d_in[5];
    const float* W2r  = (const float*)d_in[6];
    const int*   src1 = (const int*)d_in[7];
    const int*   dst1 = (const int*)d_in[8];
    const int*   src2 = (const int*)d_in[9];
    const int*   dst2 = (const int*)d_in[10];
    float* out = (float*)d_out;

    void *p;
    __half *xh, *h;
    int *cnt, *offs1, *offs2, *cur1, *cur2, *eid1, *eid2;
    __half *A1, *A2, *W1_, *W2_;
    cudaGetSymbolAddress(&p, g_xh);    xh    = (__half*)p;
    cudaGetSymbolAddress(&p, g_h);     h     = (__half*)p;
    cudaGetSymbolAddress(&p, g_cnt);   cnt   = (int*)p;
    cudaGetSymbolAddress(&p, g_offs1); offs1 = (int*)p;
    cudaGetSymbolAddress(&p, g_offs2); offs2 = (int*)p;
    cudaGetSymbolAddress(&p, g_cur1);  cur1  = (int*)p;
    cudaGetSymbolAddress(&p, g_cur2);  cur2  = (int*)p;
    cudaGetSymbolAddress(&p, g_eid1);  eid1  = (int*)p;
    cudaGetSymbolAddress(&p, g_eid2);  eid2  = (int*)p;
    cudaGetSymbolAddress(&p, g_A1);    A1    = (__half*)p;
    cudaGetSymbolAddress(&p, g_A2);    A2    = (__half*)p;
    cudaGetSymbolAddress(&p, g_W1);    W1_   = (__half*)p;
    cudaGetSymbolAddress(&p, g_W2);    W2_   = (__half*)p;

    cudaFuncSetAttribute((const void*)gemm_mma<256, 2, 0, __half>,
                         cudaFuncAttributeMaxDynamicSharedMemorySize, GEMM_SMEM);
    cudaFuncSetAttribute((const void*)gemm_mma<128, 1, 1, float>,
                         cudaFuncAttributeMaxDynamicSharedMemorySize, GEMM_SMEM);

    // (0) memset counts + 3 barrier slots (resets sw barriers every graph replay)
    cudaMemsetAsync(cnt, 0, (size_t)(N1c + N2c + 3) * sizeof(int), 0);

    // (1) prep megakernel: count -> scan|convert -> fill -> gather1
    prep_kernel<<<PREP_BLOCKS, 1024>>>(src1, dst1, src2, dst2, cnt,
                                       offs1, cur1, offs2, cur2, eid1, eid2,
                                       x, xh, W1l, W1r, W1_, W2l, W2r, W2_, A1);
    // (2) gemm1 -> fp16 h (persistent: 626 tiles on 592 CTAs)
    {
        int nTiles = ((N1c + 127) / 128) * 2;   // 626
        gemm_mma<256, 2, 0, __half><<<592, 256, GEMM_SMEM>>>(A1, W1_, b1, h, N1c, nTiles);
    }
    // (3) gather2
    gather2_kernel<<<(N2c * 32 + 255) / 256, 256>>>(h, offs2, eid2, A2);
    // (4) gemm2 -> fp32 out
    {
        int nTiles = (N2c + 127) / 128;         // 79
        gemm_mma<128, 1, 1, float><<<nTiles, 256, GEMM_SMEM>>>(A2, W2_, b2, out, N2c, nTiles);
    }
}

// round 12
// speedup vs baseline: 1.0614x; 1.0614x over previous
#include <cuda_runtime.h>
#include <cuda_fp16.h>
#include <cstdint>
#include <math.h>

// Problem constants
#define N0c 100000
#define N1c 40000
#define N2c 10000
#define E1c 640000
#define E2c 160000
#define Dc  256
#define DOUTc 128

#define GATHER1_BLOCKS (N1c / 8)   // 5000 (8 warps/block, 1 warp per dst row)
#define CS_BLOCKS      148

// ---------------- scratch (device globals) -----------------------------------
__device__ __half g_xh[(size_t)N0c * Dc];   // fp16 copy of x
__device__ __half g_h[(size_t)N1c * Dc];    // fp16 hidden layer
__device__ int   g_cnt[N1c + N2c + 2];      // counts + done-counter
__device__ int   g_offs1[N1c + 1];
__device__ int   g_offs2[N2c + 1];
__device__ int   g_cur1[N1c];
__device__ int   g_cur2[N2c];
__device__ int   g_eid1[E1c];
__device__ int   g_eid2[E2c];

__device__ __half g_A1[(size_t)N1c * 512];
__device__ __half g_A2[(size_t)N2c * 512];
__device__ __half g_W1[(size_t)Dc * 512];
__device__ __half g_W2[(size_t)DOUTc * 512];

// ---------------- PTX helpers ---------------------------------------------------

__device__ __forceinline__ uint32_t smem_u32(const void* p) {
    uint32_t a;
    asm("{ .reg .u64 t; cvta.to.shared.u64 t, %1; cvt.u32.u64 %0, t; }" : "=r"(a) : "l"(p));
    return a;
}

__device__ __forceinline__ void cp16(uint32_t dst, const void* src, uint32_t sz) {
    asm volatile("cp.async.ca.shared.global [%0], [%1], 16, %2;"
                 :: "r"(dst), "l"(src), "r"(sz) : "memory");
}
__device__ __forceinline__ void cp_commit() {
    asm volatile("cp.async.commit_group;" ::: "memory");
}
template <int N>
__device__ __forceinline__ void cp_wait() {
    asm volatile("cp.async.wait_group %0;" :: "n"(N) : "memory");
}

__device__ __forceinline__ void mma16816h(float* c, const uint32_t* a, const uint32_t* b) {
    asm volatile(
        "mma.sync.aligned.m16n8k16.row.col.f32.f16.f16.f32 "
        "{%0,%1,%2,%3}, {%4,%5,%6,%7}, {%8,%9}, {%0,%1,%2,%3};"
        : "+f"(c[0]), "+f"(c[1]), "+f"(c[2]), "+f"(c[3])
        : "r"(a[0]), "r"(a[1]), "r"(a[2]), "r"(a[3]), "r"(b[0]), "r"(b[1]));
}

__device__ __forceinline__ void ldsm4(uint32_t* r, uint32_t addr) {
    asm volatile("ldmatrix.sync.aligned.m8n8.x4.shared.b16 {%0,%1,%2,%3}, [%4];"
                 : "=r"(r[0]), "=r"(r[1]), "=r"(r[2]), "=r"(r[3]) : "r"(addr));
}

__device__ __forceinline__ uint32_t pack_h2(float a, float b) {
    __half2 h = __floats2half2_rn(a, b);
    return *(uint32_t*)&h;
}

// ---------------- count + scan + convert (persistent, sw barrier) -----------------

__global__ void count_scan_conv_kernel(const int* __restrict__ dst1,
                                       const int* __restrict__ dst2,
                                       int* __restrict__ cnt,
                                       int* __restrict__ offs1, int* __restrict__ cur1,
                                       int* __restrict__ offs2, int* __restrict__ cur2,
                                       const float* __restrict__ x, __half* __restrict__ xh,
                                       const float* __restrict__ W1l, const float* __restrict__ W1r,
                                       __half* __restrict__ W1_,
                                       const float* __restrict__ W2l, const float* __restrict__ W2r,
                                       __half* __restrict__ W2_) {
    int* done = cnt + N1c + N2c;
    const int total = E1c + E2c;
    for (int i = blockIdx.x * blockDim.x + threadIdx.x; i < total;
         i += gridDim.x * blockDim.x) {
        if (i < E1c) atomicAdd(&cnt[dst1[i]], 1);
        else         atomicAdd(&cnt[N1c + dst2[i - E1c]], 1);
    }
    __syncthreads();
    __threadfence();
    if (threadIdx.x == 0) atomicAdd(done, 1);

    if (blockIdx.x >= 2) {
        // ---- convert phase (overlaps the scans running on blocks 0,1) ----
        const int nt  = (gridDim.x - 2) * blockDim.x;
        const int tg  = (blockIdx.x - 2) * blockDim.x + threadIdx.x;
        const float4* xf = (const float4*)x;
        const int xiters = N0c * Dc / 8;
        for (int i = tg; i < xiters; i += nt) {
            float4 v0 = xf[2 * i];
            float4 v1 = xf[2 * i + 1];
            uint4 u;
            u.x = pack_h2(v0.x, v0.y);
            u.y = pack_h2(v0.z, v0.w);
            u.z = pack_h2(v1.x, v1.y);
            u.w = pack_h2(v1.z, v1.w);
            ((uint4*)xh)[i] = u;
        }
        for (int i = tg; i < Dc * 512; i += nt) {
            int n = i >> 9, k = i & 511;
            float v = (k < 256) ? W1l[(size_t)k * Dc + n] : W1r[(size_t)(k - 256) * Dc + n];
            W1_[(size_t)n * 512 + k] = __float2half_rn(v);
        }
        for (int i = tg; i < DOUTc * 512; i += nt) {
            int n = i >> 9, k = i & 511;
            float v = (k < 256) ? W2l[(size_t)k * DOUTc + n] : W2r[(size_t)(k - 256) * DOUTc + n];
            W2_[(size_t)n * 512 + k] = __float2half_rn(v);
        }
        return;
    }

    // blocks 0,1: wait for all counts, then scan one layer each
    if (threadIdx.x == 0) {
        while (*(volatile int*)done < (int)gridDim.x) { }
    }
    __syncthreads();
    __threadfence();

    const int  n  = (blockIdx.x == 0) ? N1c : N2c;
    const int* c  = (blockIdx.x == 0) ? cnt : (cnt + N1c);
    int* offs = (blockIdx.x == 0) ? offs1 : offs2;
    int* cur  = (blockIdx.x == 0) ? cur1 : cur2;

    __shared__ int warpsums[32];
    __shared__ int s_carry;
    const int lane = threadIdx.x & 31;
    const int wid  = threadIdx.x >> 5;
    const int nw   = blockDim.x >> 5;
    if (threadIdx.x == 0) s_carry = 0;
    __syncthreads();
    for (int base = 0; base < n; base += blockDim.x) {
        int i = base + threadIdx.x;
        int v = (i < n) ? c[i] : 0;
        int carry = s_carry;
        int xv = v;
        #pragma unroll
        for (int o = 1; o < 32; o <<= 1) {
            int y = __shfl_up_sync(0xFFFFFFFFu, xv, o);
            if (lane >= o) xv += y;
        }
        if (lane == 31) warpsums[wid] = xv;
        __syncthreads();
        if (wid == 0) {
            int w = (lane < nw) ? warpsums[lane] : 0;
            #pragma unroll
            for (int o = 1; o < 32; o <<= 1) {
                int y = __shfl_up_sync(0xFFFFFFFFu, w, o);
                if (lane >= o) w += y;
            }
            warpsums[lane] = w;
        }
        __syncthreads();
        int incl = xv + (wid > 0 ? warpsums[wid - 1] : 0) + carry;
        if (i < n) { offs[i] = incl - v; cur[i] = incl - v; }
        __syncthreads();
        if (threadIdx.x == blockDim.x - 1) s_carry = incl;
        __syncthreads();
    }
    if (threadIdx.x == 0) offs[n] = s_carry;
}

__global__ void fill_both_kernel(const int* __restrict__ src1, const int* __restrict__ dst1,
                                 const int* __restrict__ src2, const int* __restrict__ dst2,
                                 int* __restrict__ cur1, int* __restrict__ cur2,
                                 int* __restrict__ eid1, int* __restrict__ eid2) {
    int i = blockIdx.x * blockDim.x + threadIdx.x;
    if (i < E1c) {
        int pos = atomicAdd(&cur1[dst1[i]], 1);
        eid1[pos] = src1[i];
    } else if (i < E1c + E2c) {
        int j = i - E1c;
        int pos = atomicAdd(&cur2[dst2[j]], 1);
        eid2[pos] = src2[j];
    }
}

// ---------------- fp16 gather-mean -------------------------------------------------

__device__ __forceinline__ void acc8(float* s, uint4 v) {
    __half2* p = (__half2*)&v;
    #pragma unroll
    for (int q = 0; q < 4; q++) {
        float2 f = __half22float2(p[q]);
        s[2 * q]     += f.x;
        s[2 * q + 1] += f.y;
    }
}

__device__ __forceinline__ void gather_row_h(const __half* __restrict__ X,
                                             const int* __restrict__ offs,
                                             const int* __restrict__ eid,
                                             __half* __restrict__ A,
                                             int w, int lane) {
    int beg = offs[w], end = offs[w + 1];
    float s[8];
    #pragma unroll
    for (int q = 0; q < 8; q++) s[q] = 0.0f;

    int e = beg;
    for (; e + 1 < end; e += 2) {
        int i0 = eid[e], i1 = eid[e + 1];
        uint4 v0 = __ldg((const uint4*)(X + (size_t)i0 * Dc) + lane);
        uint4 v1 = __ldg((const uint4*)(X + (size_t)i1 * Dc) + lane);
        acc8(s, v0);
        acc8(s, v1);
    }
    if (e < end) {
        uint4 v0 = __ldg((const uint4*)(X + (size_t)eid[e] * Dc) + lane);
        acc8(s, v0);
    }
    float invd = 1.0f / (float)max(end - beg, 1);

    uint4 m;
    m.x = pack_h2(s[0] * invd, s[1] * invd);
    m.y = pack_h2(s[2] * invd, s[3] * invd);
    m.z = pack_h2(s[4] * invd, s[5] * invd);
    m.w = pack_h2(s[6] * invd, s[7] * invd);

    uint4 self = __ldg((const uint4*)(X + (size_t)w * Dc) + lane);

    __stcs((uint4*)(A + (size_t)w * 512) + lane, m);
    __stcs((uint4*)(A + (size_t)w * 512 + 256) + lane, self);
}

__global__ void gather1_kernel(const __half* __restrict__ xh,
                               const int* __restrict__ offs1, const int* __restrict__ eid1,
                               __half* __restrict__ A1) {
    int w    = blockIdx.x * 8 + (threadIdx.x >> 5);
    int lane = threadIdx.x & 31;
    if (w < N1c) gather_row_h(xh, offs1, eid1, A1, w, lane);
}

__global__ void gather2_kernel(const __half* __restrict__ h,
                               const int* __restrict__ offs2, const int* __restrict__ eid2,
                               __half* __restrict__ A2) {
    int w    = (blockIdx.x * blockDim.x + threadIdx.x) >> 5;
    int lane = threadIdx.x & 31;
    if (w < N2c) gather_row_h(h, offs2, eid2, A2, w, lane);
}

// ---------------- GEMM 1: persistent mma.sync fp16, BK=64 --------------------------
// 592 CTAs (2/SM), 626 tiles; cross-tile cp.async prefetch; epilogue overlaps prefetch.

#define ROWB64 144                        // 128B data + 16B pad (conflict-free ldmatrix)
#define MAT64  (128 * ROWB64)             // 18432
#define STAGE64 (2 * MAT64)               // 36864
#define SMEM64  (2 * STAGE64)             // 73728; 2 CTAs/SM = 147456

__global__ void __launch_bounds__(256, 2)
gemm_mma64(const __half* __restrict__ A, const __half* __restrict__ B,
           const float* __restrict__ bias, __half* __restrict__ C, int M, int nTiles)
{
    extern __shared__ char smem[];
    const uint32_t sbase = smem_u32(smem);
    const int tid  = threadIdx.x;
    const int wid  = tid >> 5;
    const int lane = tid & 31;
    const int wm   = wid >> 2;
    const int wn   = wid & 3;
    const int g    = lane >> 2;
    const int t    = lane & 3;

    const int rowoff = (lane & 7) + ((lane >> 3) & 1) * 8;
    const int koff   = (lane >> 4) * 8;
    const uint32_t lmc = (uint32_t)(rowoff * ROWB64 + koff * 2);

    if ((int)blockIdx.x >= nTiles) return;

    auto load_stage = [&](int s, int k0, int row0, int col0) {
        uint32_t base = sbase + s * STAGE64;
        #pragma unroll
        for (int q8 = 0; q8 < 8; q8++) {
            int idx  = q8 * 256 + tid;
            int mat  = idx >> 10;
            int slot = idx & 1023;
            int row  = slot >> 3;
            int quar = slot & 7;
            uint32_t dst = base + mat * MAT64 + row * ROWB64 + quar * 16;
            if (mat == 0) {
                int grow = row0 + row;
                int srow = grow < M ? grow : (M - 1);
                const __half* src = A + (size_t)srow * 512 + k0 + quar * 8;
                cp16(dst, src, grow < M ? 16u : 0u);
            } else {
                const __half* src = B + (size_t)(col0 + row) * 512 + k0 + quar * 8;
                cp16(dst, src, 16u);
            }
        }
    };

    auto tile_row0 = [&](int tl) { return (tl >> 1) * 128; };
    auto tile_col0 = [&](int tl) { return (tl & 1) * 128; };

    int tile = blockIdx.x;
    load_stage(0, 0, tile_row0(tile), tile_col0(tile));
    cp_commit();

    #pragma unroll 1
    for (; tile < nTiles; tile += gridDim.x) {
        const int row0 = tile_row0(tile);
        const int col0 = tile_col0(tile);
        const int ntile = tile + gridDim.x;

        float acc[4][4][4];
        #pragma unroll
        for (int i = 0; i < 4; i++)
            #pragma unroll
            for (int j = 0; j < 4; j++)
                #pragma unroll
                for (int q = 0; q < 4; q++) acc[i][j][q] = 0.0f;

        #pragma unroll 1
        for (int c = 0; c < 8; c++) {
            if (c < 7) {
                load_stage((c + 1) & 1, (c + 1) * 64, row0, col0);
            } else if (ntile < nTiles) {
                load_stage(0, 0, tile_row0(ntile), tile_col0(ntile));
            }
            cp_commit();
            cp_wait<1>();
            __syncthreads();

            const uint32_t st = sbase + (c & 1) * STAGE64;
            const uint32_t uA = st;
            const uint32_t uB = st + MAT64;

            #pragma unroll
            for (int kk = 0; kk < 64; kk += 16) {
                const uint32_t kb = (uint32_t)(kk * 2) + lmc;
                uint32_t b2[2][4];
                #pragma unroll
                for (int pp = 0; pp < 2; pp++) {
                    uint32_t nb = (uint32_t)((wn * 32 + pp * 16) * ROWB64) + kb;
                    ldsm4(b2[pp], uB + nb);
                }
                #pragma unroll
                for (int i = 0; i < 4; i++) {
                    uint32_t rb = (uint32_t)((wm * 64 + i * 16) * ROWB64) + kb;
                    uint32_t ah[4];
                    ldsm4(ah, uA + rb);
                    #pragma unroll
                    for (int j = 0; j < 4; j++) {
                        const int pp = j >> 1, s = j & 1;
                        uint32_t bb[2] = { b2[pp][s], b2[pp][s + 2] };
                        mma16816h(acc[i][j], ah, bb);
                    }
                }
            }
            __syncthreads();
        }

        #pragma unroll
        for (int j = 0; j < 4; j++) {
            int cidx = col0 + wn * 32 + j * 8 + 2 * t;
            float bx = bias[cidx], by = bias[cidx + 1];
            #pragma unroll
            for (int i = 0; i < 4; i++) {
                int r = row0 + wm * 64 + i * 16 + g;
                float v0 = fmaxf(acc[i][j][0] + bx, 0.f);
                float v1 = fmaxf(acc[i][j][1] + by, 0.f);
                float v2 = fmaxf(acc[i][j][2] + bx, 0.f);
                float v3 = fmaxf(acc[i][j][3] + by, 0.f);
                if (r < M)
                    *(uint32_t*)(C + (size_t)r * 256 + cidx) = pack_h2(v0, v1);
                if (r + 8 < M)
                    *(uint32_t*)(C + (size_t)(r + 8) * 256 + cidx) = pack_h2(v2, v3);
            }
        }
    }
}

// ---------------- GEMM 2: mma.sync fp16, BK=32 (R10-proven) -------------------------

#define ROWB32 80
#define MAT32  (128 * ROWB32)             // 10240
#define STAGE32 (2 * MAT32)               // 20480
#define SMEM32  (2 * STAGE32)             // 40960

__global__ void __launch_bounds__(256, 2)
gemm_mma32(const __half* __restrict__ A, const __half* __restrict__ B,
           const float* __restrict__ bias, float* __restrict__ C, int M)
{
    extern __shared__ char smem[];
    const uint32_t sbase = smem_u32(smem);
    const int tid  = threadIdx.x;
    const int wid  = tid >> 5;
    const int lane = tid & 31;
    const int wm   = wid >> 2;
    const int wn   = wid & 3;
    const int g    = lane >> 2;
    const int t    = lane & 3;

    const int row0 = blockIdx.y * 128;
    const int col0 = 0;

    const int rowoff = (lane & 7) + ((lane >> 3) & 1) * 8;
    const int koff   = (lane >> 4) * 8;
    const uint32_t lmc = (uint32_t)(rowoff * ROWB32 + koff * 2);

    float acc[4][4][4];
    #pragma unroll
    for (int i = 0; i < 4; i++)
        #pragma unroll
        for (int j = 0; j < 4; j++)
            #pragma unroll
            for (int q = 0; q < 4; q++) acc[i][j][q] = 0.0f;

    auto load_stage = [&](int s, int k0) {
        uint32_t base = sbase + s * STAGE32;
        #pragma unroll
        for (int q4 = 0; q4 < 4; q4++) {
            int idx  = q4 * 256 + tid;
            int mat  = idx >> 9;
            int slot = idx & 511;
            int row  = slot >> 2;
            int quar = slot & 3;
            uint32_t dst = base + mat * MAT32 + row * ROWB32 + quar * 16;
            if (mat == 0) {
                int grow = row0 + row;
                int srow = grow < M ? grow : (M - 1);
                const __half* src = A + (size_t)srow * 512 + k0 + quar * 8;
                cp16(dst, src, grow < M ? 16u : 0u);
            } else {
                const __half* src = B + (size_t)(col0 + row) * 512 + k0 + quar * 8;
                cp16(dst, src, 16u);
            }
        }
    };

    load_stage(0, 0);
    cp_commit();

    #pragma unroll 1
    for (int c = 0; c < 16; c++) {
        if (c < 15) {
            load_stage((c + 1) & 1, (c + 1) * 32);
            cp_commit();
            cp_wait<1>();
        } else {
            cp_wait<0>();
        }
        __syncthreads();

        const uint32_t st = sbase + (c & 1) * STAGE32;
        const uint32_t uA = st;
        const uint32_t uB = st + MAT32;

        #pragma unroll
        for (int kk = 0; kk < 32; kk += 16) {
            const uint32_t kb = (uint32_t)(kk * 2) + lmc;
            uint32_t b2[2][4];
            #pragma unroll
            for (int pp = 0; pp < 2; pp++) {
                uint32_t nb = (uint32_t)((wn * 32 + pp * 16) * ROWB32) + kb;
                ldsm4(b2[pp], uB + nb);
            }
            #pragma unroll
            for (int i = 0; i < 4; i++) {
                uint32_t rb = (uint32_t)((wm * 64 + i * 16) * ROWB32) + kb;
                uint32_t ah[4];
                ldsm4(ah, uA + rb);
                #pragma unroll
                for (int j = 0; j < 4; j++) {
                    const int pp = j >> 1, s = j & 1;
                    uint32_t bb[2] = { b2[pp][s], b2[pp][s + 2] };
                    mma16816h(acc[i][j], ah, bb);
                }
            }
        }
        __syncthreads();
    }

    #pragma unroll
    for (int j = 0; j < 4; j++) {
        int cidx = col0 + wn * 32 + j * 8 + 2 * t;
        float bx = bias[cidx], by = bias[cidx + 1];
        #pragma unroll
        for (int i = 0; i < 4; i++) {
            int r = row0 + wm * 64 + i * 16 + g;
            float v0 = 1.0f / (1.0f + expf(-(acc[i][j][0] + bx)));
            float v1 = 1.0f / (1.0f + expf(-(acc[i][j][1] + by)));
            float v2 = 1.0f / (1.0f + expf(-(acc[i][j][2] + bx)));
            float v3 = 1.0f / (1.0f + expf(-(acc[i][j][3] + by)));
            if (r < M)
                *(float2*)(C + (size_t)r * DOUTc + cidx) = make_float2(v0, v1);
            if (r + 8 < M)
                *(float2*)(C + (size_t)(r + 8) * DOUTc + cidx) = make_float2(v2, v3);
        }
    }
}

// ---------------- launch ----------------------------------------------------------

extern "C" void kernel_launch(void* const* d_in, const int* in_sizes, int n_in,
                              void* d_out, int out_size) {
    const float* x    = (const float*)d_in[0];
    const float* W1l  = (const float*)d_in[1];
    const float* b1   = (const float*)d_in[2];
    const float* W1r  = (const float*)d_in[3];
    const float* W2l  = (const float*)d_in[4];
    const float* b2   = (const float*)d_in[5];
    const float* W2r  = (const float*)d_in[6];
    const int*   src1 = (const int*)d_in[7];
    const int*   dst1 = (const int*)d_in[8];
    const int*   src2 = (const int*)d_in[9];
    const int*   dst2 = (const int*)d_in[10];
    float* out = (float*)d_out;

    void *p;
    __half *xh, *h;
    int *cnt, *offs1, *offs2, *cur1, *cur2, *eid1, *eid2;
    __half *A1, *A2, *W1_, *W2_;
    cudaGetSymbolAddress(&p, g_xh);    xh    = (__half*)p;
    cudaGetSymbolAddress(&p, g_h);     h     = (__half*)p;
    cudaGetSymbolAddress(&p, g_cnt);   cnt   = (int*)p;
    cudaGetSymbolAddress(&p, g_offs1); offs1 = (int*)p;
    cudaGetSymbolAddress(&p, g_offs2); offs2 = (int*)p;
    cudaGetSymbolAddress(&p, g_cur1);  cur1  = (int*)p;
    cudaGetSymbolAddress(&p, g_cur2);  cur2  = (int*)p;
    cudaGetSymbolAddress(&p, g_eid1);  eid1  = (int*)p;
    cudaGetSymbolAddress(&p, g_eid2);  eid2  = (int*)p;
    cudaGetSymbolAddress(&p, g_A1);    A1    = (__half*)p;
    cudaGetSymbolAddress(&p, g_A2);    A2    = (__half*)p;
    cudaGetSymbolAddress(&p, g_W1);    W1_   = (__half*)p;
    cudaGetSymbolAddress(&p, g_W2);    W2_   = (__half*)p;

    cudaFuncSetAttribute(gemm_mma64, cudaFuncAttributeMaxDynamicSharedMemorySize, SMEM64);
    cudaFuncSetAttribute(gemm_mma32, cudaFuncAttributeMaxDynamicSharedMemorySize, SMEM32);

    // (0) memset counts + done-counter
    cudaMemsetAsync(cnt, 0, (size_t)(N1c + N2c + 2) * sizeof(int), 0);

    // (1) count + scan + convert-x + convert-W (convert overlaps scan)
    count_scan_conv_kernel<<<CS_BLOCKS, 1024>>>(dst1, dst2, cnt, offs1, cur1, offs2, cur2,
                                                x, xh, W1l, W1r, W1_, W2l, W2r, W2_);
    // (2) fill both edge-id arrays
    fill_both_kernel<<<(E1c + E2c + 255) / 256, 256>>>(src1, dst1, src2, dst2,
                                                       cur1, cur2, eid1, eid2);
    // (3) gather1 (fp16 rows)
    gather1_kernel<<<GATHER1_BLOCKS, 256>>>(xh, offs1, eid1, A1);
    // (4) gemm1 -> fp16 h (persistent BK=64: 626 tiles on 592 CTAs)
    {
        int nTiles = ((N1c + 127) / 128) * 2;   // 626
        gemm_mma64<<<592, 256, SMEM64>>>(A1, W1_, b1, h, N1c, nTiles);
    }
    // (5) gather2
    gather2_kernel<<<(N2c * 32 + 255) / 256, 256>>>(h, offs2, eid2, A2);
    // (6) gemm2 -> fp32 out (BK=32, grid 79)
    {
        dim3 grid(1, (N2c + 127) / 128);
        gemm_mma32<<<grid, 256, SMEM32>>>(A2, W2_, b2, out, N2c);
    }
}